// round 11
// baseline (speedup 1.0000x reference)
#include <cuda_runtime.h>
#include <cuda_fp16.h>

#define NWIRE 480
#define NT    16
#define NN    150000
#define NE    1800000
#define NEG   0.2f
#define CAP   64          // padded bucket capacity per node (deg ~ Poisson(12))

// ---- static device scratch ----
__device__ int    g_deg[NN];                    // per-node degree (atomic cursor)
__device__ int    g_colp[(size_t)NN * CAP];     // padded adjacency: src list per dst
// transposed wires: wire-major [w][t], one float4 per (w,t)
__device__ float4 g_wt1[NWIRE * NT];
__device__ float4 g_wt2[NWIRE * NT];
__device__ float4 g_wt3[NWIRE * NT];
// rec1: per node 512B = 16 ticks x 32B (h[16] fp16). float4 index n*32 + 2t + half.
__device__ float4 g_rec1[(size_t)NN * 32];
// layer-1 attention logits, lane-indexed: float [n*32 + 2t + head]
__device__ float2 g_as12[(size_t)NN * 16];
__device__ float2 g_ad12[(size_t)NN * 16];
// rec2: per (n,t) 16B record {h2[0..1] fp16, h2[2..3] fp16, as2 f32, ad2 f32}
__device__ float4 g_rec2x[(size_t)NN * 16];

// ================= K_init: zero degree counters + transpose wires (merged) =================

__global__ void k_init(const float4* __restrict__ w1, const float4* __restrict__ w2,
                       const float4* __restrict__ w3)
{
    int i = blockIdx.x * blockDim.x + threadIdx.x;
    if (i < NN) g_deg[i] = 0;
    if (i < NT * NWIRE) {
        int t = i / NWIRE, w = i % NWIRE;
        int o = w * NT + t;
        g_wt1[o] = w1[i];
        g_wt2[o] = w2[i];
        g_wt3[o] = w3[i];
    }
}

// ================= K_append: one-pass padded-CSR build =================

__global__ void k_append(const int* __restrict__ ei) {
    int e = blockIdx.x * blockDim.x + threadIdx.x;
    if (e < NE) {
        int d   = ei[NE + e];
        int pos = atomicAdd(&g_deg[d], 1);
        if (pos < CAP) g_colp[(size_t)d * CAP + pos] = ei[e];
    }
}

// ================= K1: features + fp32 attention logits =================

__global__ void __launch_bounds__(256) k1_features(
    const int* __restrict__ idx, const float* __restrict__ W1,
    const float* __restrict__ a1s, const float* __restrict__ a1d)
{
    __shared__ float4 sW4[48];                  // W1 [12][16] as 12 rows x 4 float4
    __shared__ float  ss[16], sd[16];
    int tid = threadIdx.x;
    if (tid < 48) sW4[tid] = ((const float4*)W1)[tid];
    if (tid >= 64 && tid < 80) ss[tid - 64] = a1s[tid - 64];
    if (tid >= 80 && tid < 96) sd[tid - 80] = a1d[tid - 80];
    __syncthreads();

    int n = blockIdx.x * 16 + (tid >> 4);
    int t = tid & 15;
    if (n >= NN) return;

    int i0 = idx[3 * n], i1 = idx[3 * n + 1], i2 = idx[3 * n + 2];
    float4 x0 = g_wt1[i0 * NT + t];   // 16 lanes of one node: 256B contiguous
    float4 x1 = g_wt2[i1 * NT + t];
    float4 x2 = g_wt3[i2 * NT + t];
    float x[12] = { x0.x, x0.y, x0.z, x0.w, x1.x, x1.y, x1.z, x1.w, x2.x, x2.y, x2.z, x2.w };

    float4 h0 = make_float4(0.f, 0.f, 0.f, 0.f);
    float4 h1 = h0, h2 = h0, h3 = h0;
#pragma unroll
    for (int k = 0; k < 12; k++) {
        float xk = x[k];
        float4 w0 = sW4[k * 4], w1 = sW4[k * 4 + 1], w2 = sW4[k * 4 + 2], w3 = sW4[k * 4 + 3];
        h0.x += xk * w0.x; h0.y += xk * w0.y; h0.z += xk * w0.z; h0.w += xk * w0.w;
        h1.x += xk * w1.x; h1.y += xk * w1.y; h1.z += xk * w1.z; h1.w += xk * w1.w;
        h2.x += xk * w2.x; h2.y += xk * w2.y; h2.z += xk * w2.z; h2.w += xk * w2.w;
        h3.x += xk * w3.x; h3.y += xk * w3.y; h3.z += xk * w3.z; h3.w += xk * w3.w;
    }

    // fp32 attention logits per head
    float as0 = h0.x*ss[0] + h0.y*ss[1] + h0.z*ss[2] + h0.w*ss[3]
              + h1.x*ss[4] + h1.y*ss[5] + h1.z*ss[6] + h1.w*ss[7];
    float as1 = h2.x*ss[8] + h2.y*ss[9] + h2.z*ss[10] + h2.w*ss[11]
              + h3.x*ss[12] + h3.y*ss[13] + h3.z*ss[14] + h3.w*ss[15];
    float ad0 = h0.x*sd[0] + h0.y*sd[1] + h0.z*sd[2] + h0.w*sd[3]
              + h1.x*sd[4] + h1.y*sd[5] + h1.z*sd[6] + h1.w*sd[7];
    float ad1 = h2.x*sd[8] + h2.y*sd[9] + h2.z*sd[10] + h2.w*sd[11]
              + h3.x*sd[12] + h3.y*sd[13] + h3.z*sd[14] + h3.w*sd[15];

    float4 p0, p1;
    half2* ha = (half2*)&p0;
    half2* hb = (half2*)&p1;
    ha[0] = __floats2half2_rn(h0.x, h0.y); ha[1] = __floats2half2_rn(h0.z, h0.w);
    ha[2] = __floats2half2_rn(h1.x, h1.y); ha[3] = __floats2half2_rn(h1.z, h1.w);
    hb[0] = __floats2half2_rn(h2.x, h2.y); hb[1] = __floats2half2_rn(h2.z, h2.w);
    hb[2] = __floats2half2_rn(h3.x, h3.y); hb[3] = __floats2half2_rn(h3.z, h3.w);

    size_t base = (size_t)n * 32 + t * 2;
    g_rec1[base]     = p0;
    g_rec1[base + 1] = p1;
    g_as12[(size_t)n * 16 + t] = make_float2(as0, as1);   // float view: [n*32 + 2t + hd]
    g_ad12[(size_t)n * 16 + t] = make_float2(ad0, ad1);
}

// ================= K2: warp-per-node layer-1 aggregate, 4-deep, precomputed logits =========

__device__ __forceinline__ void unpack8(const float4& p, float* f) {
    const half2* hh = (const half2*)&p;
#pragma unroll
    for (int j = 0; j < 4; j++) {
        float2 v = __half22float2(hh[j]);
        f[2 * j] = v.x; f[2 * j + 1] = v.y;
    }
}

__global__ void __launch_bounds__(256) k2_agg1(
    const float* __restrict__ W2,
    const float* __restrict__ a2s, const float* __restrict__ a2d)
{
    __shared__ float sW[64], s2s[4], s2d[4];
    int tid = threadIdx.x;
    if (tid < 64) sW[tid] = W2[tid];
    if (tid >= 64 && tid < 68) { s2s[tid - 64] = a2s[tid - 64]; s2d[tid - 64] = a2d[tid - 64]; }
    __syncthreads();

    int n = blockIdx.x * 8 + (tid >> 5);
    if (n >= NN) return;
    int lane = tid & 31;
    int hd   = lane & 1;                 // head

    const char*  rbase = (const char*)g_rec1;
    const float* gas   = (const float*)g_as12;
    const float* gad   = (const float*)g_ad12;
    unsigned lane16 = (unsigned)lane * 16u;

    float ad = gad[(size_t)n * 32 + lane];      // my dst logit (fp32, from k1)

    int deg = g_deg[n];
    const int* col = g_colp + (size_t)n * CAP;

    float acc[8] = {0.f, 0.f, 0.f, 0.f, 0.f, 0.f, 0.f, 0.f};
    float den = 0.f;

    auto proc = [&](const float4& p, float as) {
        float g[8];
        unpack8(p, g);
        float z = as + ad; z = z > 0.f ? z : NEG * z;
        float w = __expf(z);
        den += w;
#pragma unroll
        for (int d = 0; d < 8; d++) acc[d] += w * g[d];
    };

    if (deg > 0) {
        int last = deg - 1;
        float4 c[4]; float ca[4];
#pragma unroll
        for (int k = 0; k < 4; k++) {
            int s = col[min(k, last)];
            c[k]  = *(const float4*)(rbase + ((size_t)((unsigned)s * 512u + lane16)));
            ca[k] = gas[(size_t)s * 32 + lane];
        }
        for (int e = 0; e < deg; e += 4) {
            int si[4];
#pragma unroll
            for (int k = 0; k < 4; k++) si[k] = col[min(e + 4 + k, last)];
            float4 nx[4]; float na[4];
#pragma unroll
            for (int k = 0; k < 4; k++) {
                nx[k] = *(const float4*)(rbase + ((size_t)((unsigned)si[k] * 512u + lane16)));
                na[k] = gas[(size_t)si[k] * 32 + lane];
            }
            proc(c[0], ca[0]);
            if (e + 1 < deg) proc(c[1], ca[1]);
            if (e + 2 < deg) proc(c[2], ca[2]);
            if (e + 3 < deg) proc(c[3], ca[3]);
#pragma unroll
            for (int k = 0; k < 4; k++) { c[k] = nx[k]; ca[k] = na[k]; }
        }
    }

    float inv = 1.f / fmaxf(den, 1e-16f);
    float o[8];
#pragma unroll
    for (int d = 0; d < 8; d++) {
        float v = acc[d] * inv;
        o[d] = v > 0.f ? v : (__expf(v) - 1.f);              // ELU
    }

    // W2: my 8 rows -> partial h2o[4]; pair-sum with the other head via shfl_xor(1)
    const float* sWh = sW + hd * 32;
    float h2o[4] = {0.f, 0.f, 0.f, 0.f};
#pragma unroll
    for (int d = 0; d < 8; d++) {
        float od = o[d];
#pragma unroll
        for (int c2 = 0; c2 < 4; c2++) h2o[c2] += od * sWh[d * 4 + c2];
    }
#pragma unroll
    for (int c2 = 0; c2 < 4; c2++) h2o[c2] += __shfl_xor_sync(0xffffffffu, h2o[c2], 1);

    if (hd == 0) {
        int t = lane >> 1;
        float as2 = h2o[0]*s2s[0] + h2o[1]*s2s[1] + h2o[2]*s2s[2] + h2o[3]*s2s[3];
        float ad2 = h2o[0]*s2d[0] + h2o[1]*s2d[1] + h2o[2]*s2d[2] + h2o[3]*s2d[3];
        float4 w4;
        half2* hw = (half2*)&w4;
        hw[0] = __floats2half2_rn(h2o[0], h2o[1]);
        hw[1] = __floats2half2_rn(h2o[2], h2o[3]);
        w4.z = as2;
        w4.w = ad2;
        g_rec2x[(size_t)n * 16 + t] = w4;
    }
}

// ================= K3: warp-per-node layer-2 aggregate + MLP =================

__global__ void __launch_bounds__(256) k3_agg2(
    const float* __restrict__ mw, const float* __restrict__ mb,
    float* __restrict__ out)
{
    __shared__ float sm[4], sb;
    int tid = threadIdx.x;
    if (tid < 4) sm[tid] = mw[tid];
    if (tid == 4) sb = mb[0];
    __syncthreads();

    int n = blockIdx.x * 8 + (tid >> 5);
    if (n >= NN) return;
    int lane = tid & 31;
    int t    = lane & 15;
    int a    = lane >> 4;            // which edge of each pair this lane handles

    const char* rbase = (const char*)g_rec2x;
    unsigned t16 = (unsigned)t * 16u;

    float ad = g_rec2x[(size_t)n * 16 + t].w;   // my dst logit (fp32)

    int deg = g_deg[n];
    const int* col = g_colp + (size_t)n * CAP;

    float a0 = 0.f, a1 = 0.f, a2 = 0.f, a3 = 0.f, den = 0.f;

    auto proc = [&](const float4& v) {
        const half2* hh = (const half2*)&v;
        float2 f0 = __half22float2(hh[0]), f1 = __half22float2(hh[1]);
        float z = v.z + ad; z = z > 0.f ? z : NEG * z;
        float w = __expf(z);
        den += w;
        a0 += w * f0.x; a1 += w * f0.y; a2 += w * f1.x; a3 += w * f1.y;
    };

    if (deg > 0) {
        int last = deg - 1;
        float4 v[4];                                   // lane covers edges e+2k+a, k=0..3
#pragma unroll
        for (int k = 0; k < 4; k++) {
            int s = col[min(2 * k + a, last)];
            v[k] = *(const float4*)(rbase + ((size_t)((unsigned)s * 256u + t16)));
        }
        for (int e = 0; e < deg; e += 8) {
            int si[4];
#pragma unroll
            for (int k = 0; k < 4; k++) si[k] = col[min(e + 8 + 2 * k + a, last)];
            float4 nx[4];
#pragma unroll
            for (int k = 0; k < 4; k++)
                nx[k] = *(const float4*)(rbase + ((size_t)((unsigned)si[k] * 256u + t16)));
#pragma unroll
            for (int k = 0; k < 4; k++)
                if (e + 2 * k + a < deg) proc(v[k]);
#pragma unroll
            for (int k = 0; k < 4; k++) v[k] = nx[k];
        }
    }

    // combine the two edge-halves for each tick
    a0  += __shfl_down_sync(0xffffffffu, a0, 16);
    a1  += __shfl_down_sync(0xffffffffu, a1, 16);
    a2  += __shfl_down_sync(0xffffffffu, a2, 16);
    a3  += __shfl_down_sync(0xffffffffu, a3, 16);
    den += __shfl_down_sync(0xffffffffu, den, 16);

    if (a == 0) {
        float inv = 1.f / fmaxf(den, 1e-16f);
        float y = (a0 * sm[0] + a1 * sm[1] + a2 * sm[2] + a3 * sm[3]) * inv + sb;
        out[(size_t)t * NN + n] = y;
    }
}

// ================= launch =================

extern "C" void kernel_launch(void* const* d_in, const int* in_sizes, int n_in,
                              void* d_out, int out_size)
{
    const float* fw  = (const float*)d_in[0];
    const float* sw  = (const float*)d_in[1];
    const float* tw  = (const float*)d_in[2];
    const int*   idx = (const int*)  d_in[3];
    const int*   ei  = (const int*)  d_in[4];
    const float* W1  = (const float*)d_in[5];
    const float* a1s = (const float*)d_in[6];
    const float* a1d = (const float*)d_in[7];
    const float* W2  = (const float*)d_in[8];
    const float* a2s = (const float*)d_in[9];
    const float* a2d = (const float*)d_in[10];
    const float* mw  = (const float*)d_in[11];
    const float* mb  = (const float*)d_in[12];
    float* out = (float*)d_out;

    k_init<<<(NN + 255) / 256, 256>>>((const float4*)fw, (const float4*)sw, (const float4*)tw);
    k_append<<<(NE + 255) / 256, 256>>>(ei);
    k1_features<<<(NN + 15) / 16, 256>>>(idx, W1, a1s, a1d);
    k2_agg1<<<(NN + 7) / 8, 256>>>(W2, a2s, a2d);
    k3_agg2<<<(NN + 7) / 8, 256>>>(mw, mb, out);
}

// round 12
// speedup vs baseline: 1.0951x; 1.0951x over previous
#include <cuda_runtime.h>
#include <cuda_fp16.h>

#define NWIRE 480
#define NT    16
#define NN    150000
#define NE    1800000
#define NEG   0.2f
#define CAP   64          // padded bucket capacity per node (deg ~ Poisson(12))

// ---- static device scratch ----
__device__ int    g_deg[NN];                    // per-node degree; after k1: PADDED degree
__device__ int    g_colp[(size_t)NN * CAP];     // padded adjacency: src list per dst
// transposed wires: wire-major [w][t], one float4 per (w,t)
__device__ float4 g_wt1[NWIRE * NT];
__device__ float4 g_wt2[NWIRE * NT];
__device__ float4 g_wt3[NWIRE * NT];
// rec1: per node 512B = 16 ticks x 32B (h[16] fp16); +1 sentinel node (index NN, all zero)
__device__ float4 g_rec1[(size_t)(NN + 1) * 32];
// layer-1 attention logits, lane-indexed float [n*32 + 2t + head]; sentinel = -1e30
__device__ float2 g_as12[(size_t)(NN + 1) * 16];
__device__ float2 g_ad12[(size_t)(NN + 1) * 16];
// rec2: per (n,t) 16B {h2[0..3] fp16, as2 f32, ad2 f32}; sentinel as2 = -1e30
__device__ float4 g_rec2x[(size_t)(NN + 1) * 16];

// ================= K_init: zero deg + transpose wires + write sentinel records =============

__global__ void k_init(const float4* __restrict__ w1, const float4* __restrict__ w2,
                       const float4* __restrict__ w3)
{
    int i = blockIdx.x * blockDim.x + threadIdx.x;
    if (i < NN) g_deg[i] = 0;
    if (i < NT * NWIRE) {
        int t = i / NWIRE, w = i % NWIRE;
        int o = w * NT + t;
        g_wt1[o] = w1[i];
        g_wt2[o] = w2[i];
        g_wt3[o] = w3[i];
    }
    if (i < 32) {
        g_rec1[(size_t)NN * 32 + i] = make_float4(0.f, 0.f, 0.f, 0.f);
        if (i < 16) {
            g_as12[(size_t)NN * 16 + i] = make_float2(-1e30f, -1e30f);
            g_ad12[(size_t)NN * 16 + i] = make_float2(0.f, 0.f);
            g_rec2x[(size_t)NN * 16 + i] = make_float4(0.f, 0.f, -1e30f, 0.f);
        }
    }
}

// ================= K_append: one-pass padded-CSR build =================

__global__ void k_append(const int* __restrict__ ei) {
    int e = blockIdx.x * blockDim.x + threadIdx.x;
    if (e < NE) {
        int d   = ei[NE + e];
        int pos = atomicAdd(&g_deg[d], 1);
        if (pos < CAP) g_colp[(size_t)d * CAP + pos] = ei[e];
    }
}

// ================= K1: features + fp32 logits; lane 0 pads adjacency to 8-multiple =========

__global__ void __launch_bounds__(256) k1_features(
    const int* __restrict__ idx, const float* __restrict__ W1,
    const float* __restrict__ a1s, const float* __restrict__ a1d)
{
    __shared__ float4 sW4[48];                  // W1 [12][16] as 12 rows x 4 float4
    __shared__ float  ss[16], sd[16];
    int tid = threadIdx.x;
    if (tid < 48) sW4[tid] = ((const float4*)W1)[tid];
    if (tid >= 64 && tid < 80) ss[tid - 64] = a1s[tid - 64];
    if (tid >= 80 && tid < 96) sd[tid - 80] = a1d[tid - 80];
    __syncthreads();

    int n = blockIdx.x * 16 + (tid >> 4);
    int t = tid & 15;
    if (n >= NN) return;

    // pad adjacency with sentinel (index NN) to a multiple of 8; store padded degree
    if (t == 0) {
        int dg = min(g_deg[n], CAP);
        int dp = min((dg + 7) & ~7, CAP);
        for (int j = dg; j < dp; j++) g_colp[(size_t)n * CAP + j] = NN;
        g_deg[n] = dp;
    }

    int i0 = idx[3 * n], i1 = idx[3 * n + 1], i2 = idx[3 * n + 2];
    float4 x0 = g_wt1[i0 * NT + t];   // 16 lanes of one node: 256B contiguous
    float4 x1 = g_wt2[i1 * NT + t];
    float4 x2 = g_wt3[i2 * NT + t];
    float x[12] = { x0.x, x0.y, x0.z, x0.w, x1.x, x1.y, x1.z, x1.w, x2.x, x2.y, x2.z, x2.w };

    float4 h0 = make_float4(0.f, 0.f, 0.f, 0.f);
    float4 h1 = h0, h2 = h0, h3 = h0;
#pragma unroll
    for (int k = 0; k < 12; k++) {
        float xk = x[k];
        float4 w0 = sW4[k * 4], w1 = sW4[k * 4 + 1], w2 = sW4[k * 4 + 2], w3 = sW4[k * 4 + 3];
        h0.x += xk * w0.x; h0.y += xk * w0.y; h0.z += xk * w0.z; h0.w += xk * w0.w;
        h1.x += xk * w1.x; h1.y += xk * w1.y; h1.z += xk * w1.z; h1.w += xk * w1.w;
        h2.x += xk * w2.x; h2.y += xk * w2.y; h2.z += xk * w2.z; h2.w += xk * w2.w;
        h3.x += xk * w3.x; h3.y += xk * w3.y; h3.z += xk * w3.z; h3.w += xk * w3.w;
    }

    float as0 = h0.x*ss[0] + h0.y*ss[1] + h0.z*ss[2] + h0.w*ss[3]
              + h1.x*ss[4] + h1.y*ss[5] + h1.z*ss[6] + h1.w*ss[7];
    float as1 = h2.x*ss[8] + h2.y*ss[9] + h2.z*ss[10] + h2.w*ss[11]
              + h3.x*ss[12] + h3.y*ss[13] + h3.z*ss[14] + h3.w*ss[15];
    float ad0 = h0.x*sd[0] + h0.y*sd[1] + h0.z*sd[2] + h0.w*sd[3]
              + h1.x*sd[4] + h1.y*sd[5] + h1.z*sd[6] + h1.w*sd[7];
    float ad1 = h2.x*sd[8] + h2.y*sd[9] + h2.z*sd[10] + h2.w*sd[11]
              + h3.x*sd[12] + h3.y*sd[13] + h3.z*sd[14] + h3.w*sd[15];

    float4 p0, p1;
    half2* ha = (half2*)&p0;
    half2* hb = (half2*)&p1;
    ha[0] = __floats2half2_rn(h0.x, h0.y); ha[1] = __floats2half2_rn(h0.z, h0.w);
    ha[2] = __floats2half2_rn(h1.x, h1.y); ha[3] = __floats2half2_rn(h1.z, h1.w);
    hb[0] = __floats2half2_rn(h2.x, h2.y); hb[1] = __floats2half2_rn(h2.z, h2.w);
    hb[2] = __floats2half2_rn(h3.x, h3.y); hb[3] = __floats2half2_rn(h3.z, h3.w);

    size_t base = (size_t)n * 32 + t * 2;
    g_rec1[base]     = p0;
    g_rec1[base + 1] = p1;
    g_as12[(size_t)n * 16 + t] = make_float2(as0, as1);
    g_ad12[(size_t)n * 16 + t] = make_float2(ad0, ad1);
}

// ================= K2: warp-per-node layer-1 aggregate, branchless sentinel loop ==========

__device__ __forceinline__ void unpack8(const float4& p, float* f) {
    const half2* hh = (const half2*)&p;
#pragma unroll
    for (int j = 0; j < 4; j++) {
        float2 v = __half22float2(hh[j]);
        f[2 * j] = v.x; f[2 * j + 1] = v.y;
    }
}

__global__ void __launch_bounds__(256) k2_agg1(
    const float* __restrict__ W2,
    const float* __restrict__ a2s, const float* __restrict__ a2d)
{
    __shared__ float sW[64], s2s[4], s2d[4];
    int tid = threadIdx.x;
    if (tid < 64) sW[tid] = W2[tid];
    if (tid >= 64 && tid < 68) { s2s[tid - 64] = a2s[tid - 64]; s2d[tid - 64] = a2d[tid - 64]; }
    __syncthreads();

    int n = blockIdx.x * 8 + (tid >> 5);
    if (n >= NN) return;
    int lane = tid & 31;
    int hd   = lane & 1;                 // head

    const char*  rbase = (const char*)g_rec1;
    const float* gas   = (const float*)g_as12;
    const float* gad   = (const float*)g_ad12;
    unsigned lane16 = (unsigned)lane * 16u;

    float ad = gad[(size_t)n * 32 + lane];      // my dst logit (fp32)

    int dp = g_deg[n];                          // padded degree (multiple of 8, or 0)
    const int* col = g_colp + (size_t)n * CAP;

    float acc[8] = {0.f, 0.f, 0.f, 0.f, 0.f, 0.f, 0.f, 0.f};
    float den = 0.f;

    auto proc = [&](const float4& p, float as) {
        float g[8];
        unpack8(p, g);
        float z = as + ad; z = z > 0.f ? z : NEG * z;
        float w = __expf(z);
        den += w;
#pragma unroll
        for (int d = 0; d < 8; d++) acc[d] += w * g[d];
    };

    if (dp > 0) {
        const int4* cp = (const int4*)col;      // 256B-aligned bucket
        int nbatch = dp >> 2;                   // even, >= 2
        int lastb  = nbatch - 1;
        int4 cs = cp[0];
        float4 c0 = *(const float4*)(rbase + (size_t)((unsigned)cs.x * 512u + lane16));
        float4 c1 = *(const float4*)(rbase + (size_t)((unsigned)cs.y * 512u + lane16));
        float4 c2 = *(const float4*)(rbase + (size_t)((unsigned)cs.z * 512u + lane16));
        float4 c3 = *(const float4*)(rbase + (size_t)((unsigned)cs.w * 512u + lane16));
        float ca0 = gas[(size_t)cs.x * 32 + lane];
        float ca1 = gas[(size_t)cs.y * 32 + lane];
        float ca2 = gas[(size_t)cs.z * 32 + lane];
        float ca3 = gas[(size_t)cs.w * 32 + lane];
        for (int b = 0; b < nbatch; b++) {
            int nb = min(b + 1, lastb);
            int4 ns = cp[nb];
            float4 n0 = *(const float4*)(rbase + (size_t)((unsigned)ns.x * 512u + lane16));
            float4 n1 = *(const float4*)(rbase + (size_t)((unsigned)ns.y * 512u + lane16));
            float4 n2 = *(const float4*)(rbase + (size_t)((unsigned)ns.z * 512u + lane16));
            float4 n3 = *(const float4*)(rbase + (size_t)((unsigned)ns.w * 512u + lane16));
            float na0 = gas[(size_t)ns.x * 32 + lane];
            float na1 = gas[(size_t)ns.y * 32 + lane];
            float na2 = gas[(size_t)ns.z * 32 + lane];
            float na3 = gas[(size_t)ns.w * 32 + lane];
            proc(c0, ca0);                       // unconditional: sentinels give w = 0
            proc(c1, ca1);
            proc(c2, ca2);
            proc(c3, ca3);
            c0 = n0; c1 = n1; c2 = n2; c3 = n3;
            ca0 = na0; ca1 = na1; ca2 = na2; ca3 = na3;
        }
    }

    float inv = 1.f / fmaxf(den, 1e-16f);
    float o[8];
#pragma unroll
    for (int d = 0; d < 8; d++) {
        float v = acc[d] * inv;
        o[d] = v > 0.f ? v : (__expf(v) - 1.f);              // ELU
    }

    // W2: my 8 rows -> partial h2o[4]; pair-sum with the other head via shfl_xor(1)
    const float* sWh = sW + hd * 32;
    float h2o[4] = {0.f, 0.f, 0.f, 0.f};
#pragma unroll
    for (int d = 0; d < 8; d++) {
        float od = o[d];
#pragma unroll
        for (int c2 = 0; c2 < 4; c2++) h2o[c2] += od * sWh[d * 4 + c2];
    }
#pragma unroll
    for (int c2 = 0; c2 < 4; c2++) h2o[c2] += __shfl_xor_sync(0xffffffffu, h2o[c2], 1);

    if (hd == 0) {
        int t = lane >> 1;
        float as2 = h2o[0]*s2s[0] + h2o[1]*s2s[1] + h2o[2]*s2s[2] + h2o[3]*s2s[3];
        float ad2 = h2o[0]*s2d[0] + h2o[1]*s2d[1] + h2o[2]*s2d[2] + h2o[3]*s2d[3];
        float4 w4;
        half2* hw = (half2*)&w4;
        hw[0] = __floats2half2_rn(h2o[0], h2o[1]);
        hw[1] = __floats2half2_rn(h2o[2], h2o[3]);
        w4.z = as2;
        w4.w = ad2;
        g_rec2x[(size_t)n * 16 + t] = w4;
    }
}

// ================= K3: warp-per-node layer-2 aggregate + MLP, branchless ==============

__global__ void __launch_bounds__(256) k3_agg2(
    const float* __restrict__ mw, const float* __restrict__ mb,
    float* __restrict__ out)
{
    __shared__ float sm[4], sb;
    int tid = threadIdx.x;
    if (tid < 4) sm[tid] = mw[tid];
    if (tid == 4) sb = mb[0];
    __syncthreads();

    int n = blockIdx.x * 8 + (tid >> 5);
    if (n >= NN) return;
    int lane = tid & 31;
    int t    = lane & 15;
    int a    = lane >> 4;            // which edge of each pair this lane handles

    const char* rbase = (const char*)g_rec2x;
    unsigned t16 = (unsigned)t * 16u;

    float ad = g_rec2x[(size_t)n * 16 + t].w;   // my dst logit (fp32)

    int dp = g_deg[n];                          // padded degree (multiple of 8, or 0)
    const int* col = g_colp + (size_t)n * CAP;

    float a0 = 0.f, a1 = 0.f, a2 = 0.f, a3 = 0.f, den = 0.f;

    auto proc = [&](const float4& v) {
        const half2* hh = (const half2*)&v;
        float2 f0 = __half22float2(hh[0]), f1 = __half22float2(hh[1]);
        float z = v.z + ad; z = z > 0.f ? z : NEG * z;
        float w = __expf(z);
        den += w;
        a0 += w * f0.x; a1 += w * f0.y; a2 += w * f1.x; a3 += w * f1.y;
    };

    if (dp > 0) {
        int nbatch = dp >> 3;                   // >= 1
        int lastb  = nbatch - 1;
        int j0 = col[a], j1 = col[2 + a], j2 = col[4 + a], j3 = col[6 + a];
        float4 v0 = *(const float4*)(rbase + (size_t)((unsigned)j0 * 256u + t16));
        float4 v1 = *(const float4*)(rbase + (size_t)((unsigned)j1 * 256u + t16));
        float4 v2 = *(const float4*)(rbase + (size_t)((unsigned)j2 * 256u + t16));
        float4 v3 = *(const float4*)(rbase + (size_t)((unsigned)j3 * 256u + t16));
        for (int b = 0; b < nbatch; b++) {
            int base = min(b + 1, lastb) << 3;
            int k0 = col[base + a],     k1 = col[base + 2 + a];
            int k2 = col[base + 4 + a], k3 = col[base + 6 + a];
            float4 n0 = *(const float4*)(rbase + (size_t)((unsigned)k0 * 256u + t16));
            float4 n1 = *(const float4*)(rbase + (size_t)((unsigned)k1 * 256u + t16));
            float4 n2 = *(const float4*)(rbase + (size_t)((unsigned)k2 * 256u + t16));
            float4 n3 = *(const float4*)(rbase + (size_t)((unsigned)k3 * 256u + t16));
            proc(v0);                            // unconditional: sentinels give w = 0
            proc(v1);
            proc(v2);
            proc(v3);
            v0 = n0; v1 = n1; v2 = n2; v3 = n3;
        }
    }

    // combine the two edge-halves for each tick
    a0  += __shfl_down_sync(0xffffffffu, a0, 16);
    a1  += __shfl_down_sync(0xffffffffu, a1, 16);
    a2  += __shfl_down_sync(0xffffffffu, a2, 16);
    a3  += __shfl_down_sync(0xffffffffu, a3, 16);
    den += __shfl_down_sync(0xffffffffu, den, 16);

    if (a == 0) {
        float inv = 1.f / fmaxf(den, 1e-16f);
        float y = (a0 * sm[0] + a1 * sm[1] + a2 * sm[2] + a3 * sm[3]) * inv + sb;
        out[(size_t)t * NN + n] = y;
    }
}

// ================= launch =================

extern "C" void kernel_launch(void* const* d_in, const int* in_sizes, int n_in,
                              void* d_out, int out_size)
{
    const float* fw  = (const float*)d_in[0];
    const float* sw  = (const float*)d_in[1];
    const float* tw  = (const float*)d_in[2];
    const int*   idx = (const int*)  d_in[3];
    const int*   ei  = (const int*)  d_in[4];
    const float* W1  = (const float*)d_in[5];
    const float* a1s = (const float*)d_in[6];
    const float* a1d = (const float*)d_in[7];
    const float* W2  = (const float*)d_in[8];
    const float* a2s = (const float*)d_in[9];
    const float* a2d = (const float*)d_in[10];
    const float* mw  = (const float*)d_in[11];
    const float* mb  = (const float*)d_in[12];
    float* out = (float*)d_out;

    // k2 is the 4th kernel launch -> lands in the profiled slot
    k_init<<<(NN + 255) / 256, 256>>>((const float4*)fw, (const float4*)sw, (const float4*)tw);
    k_append<<<(NE + 255) / 256, 256>>>(ei);
    k1_features<<<(NN + 15) / 16, 256>>>(idx, W1, a1s, a1d);
    k2_agg1<<<(NN + 7) / 8, 256>>>(W2, a2s, a2d);
    k3_agg2<<<(NN + 7) / 8, 256>>>(mw, mb, out);
}

// round 13
// speedup vs baseline: 1.2113x; 1.1061x over previous
#include <cuda_runtime.h>
#include <cuda_fp16.h>

#define NWIRE 480
#define NT    16
#define NN    150000
#define NE    1800000
#define NEG   0.2f
#define CAP   64          // padded bucket capacity per node (deg ~ Poisson(12))

// ---- static device scratch ----
__device__ int    g_deg[NN];                    // per-node degree; after k1: PADDED degree
__device__ int    g_colp[(size_t)NN * CAP];     // padded adjacency: src list per dst
// transposed wires: wire-major [w][t], one float4 per (w,t)
__device__ float4 g_wt1[NWIRE * NT];
__device__ float4 g_wt2[NWIRE * NT];
__device__ float4 g_wt3[NWIRE * NT];
// rec1: per node 512B = 16 ticks x 32B (h[16] fp16); +1 sentinel node (index NN, all zero)
__device__ float4 g_rec1[(size_t)(NN + 1) * 32];
// layer-1 attention logits, lane-indexed float [n*32 + 2t + head]; sentinel = -1e30
__device__ float2 g_as12[(size_t)(NN + 1) * 16];
__device__ float2 g_ad12[(size_t)(NN + 1) * 16];
// rec2: per (n,t) 16B {h2[0..3] fp16, as2 f32, ad2 f32}; sentinel as2 = -1e30
__device__ float4 g_rec2x[(size_t)(NN + 1) * 16];

// ================= K_init: zero deg + transpose wires + write sentinel records =============

__global__ void k_init(const float4* __restrict__ w1, const float4* __restrict__ w2,
                       const float4* __restrict__ w3)
{
    int i = blockIdx.x * blockDim.x + threadIdx.x;
    if (i < NN) g_deg[i] = 0;
    if (i < NT * NWIRE) {
        int t = i / NWIRE, w = i % NWIRE;
        int o = w * NT + t;
        g_wt1[o] = w1[i];
        g_wt2[o] = w2[i];
        g_wt3[o] = w3[i];
    }
    if (i < 32) {
        g_rec1[(size_t)NN * 32 + i] = make_float4(0.f, 0.f, 0.f, 0.f);
        if (i < 16) {
            g_as12[(size_t)NN * 16 + i] = make_float2(-1e30f, -1e30f);
            g_ad12[(size_t)NN * 16 + i] = make_float2(0.f, 0.f);
            g_rec2x[(size_t)NN * 16 + i] = make_float4(0.f, 0.f, -1e30f, 0.f);
        }
    }
}

// ================= K_append: one-pass padded-CSR build =================

__global__ void k_append(const int* __restrict__ ei) {
    int e = blockIdx.x * blockDim.x + threadIdx.x;
    if (e < NE) {
        int d   = ei[NE + e];
        int pos = atomicAdd(&g_deg[d], 1);
        if (pos < CAP) g_colp[(size_t)d * CAP + pos] = ei[e];
    }
}

// ================= K1: features + fp32 logits; lane 0 pads adjacency to 4-multiple =========

__global__ void __launch_bounds__(256) k1_features(
    const int* __restrict__ idx, const float* __restrict__ W1,
    const float* __restrict__ a1s, const float* __restrict__ a1d)
{
    __shared__ float4 sW4[48];                  // W1 [12][16] as 12 rows x 4 float4
    __shared__ float  ss[16], sd[16];
    int tid = threadIdx.x;
    if (tid < 48) sW4[tid] = ((const float4*)W1)[tid];
    if (tid >= 64 && tid < 80) ss[tid - 64] = a1s[tid - 64];
    if (tid >= 80 && tid < 96) sd[tid - 80] = a1d[tid - 80];
    __syncthreads();

    int n = blockIdx.x * 16 + (tid >> 4);
    int t = tid & 15;
    if (n >= NN) return;

    // pad adjacency with sentinel (index NN) to a multiple of 4; store padded degree
    if (t == 0) {
        int dg = min(g_deg[n], CAP);
        int dp = min((dg + 3) & ~3, CAP);
        for (int j = dg; j < dp; j++) g_colp[(size_t)n * CAP + j] = NN;
        g_deg[n] = dp;
    }

    int i0 = idx[3 * n], i1 = idx[3 * n + 1], i2 = idx[3 * n + 2];
    float4 x0 = g_wt1[i0 * NT + t];   // 16 lanes of one node: 256B contiguous
    float4 x1 = g_wt2[i1 * NT + t];
    float4 x2 = g_wt3[i2 * NT + t];
    float x[12] = { x0.x, x0.y, x0.z, x0.w, x1.x, x1.y, x1.z, x1.w, x2.x, x2.y, x2.z, x2.w };

    float4 h0 = make_float4(0.f, 0.f, 0.f, 0.f);
    float4 h1 = h0, h2 = h0, h3 = h0;
#pragma unroll
    for (int k = 0; k < 12; k++) {
        float xk = x[k];
        float4 w0 = sW4[k * 4], w1 = sW4[k * 4 + 1], w2 = sW4[k * 4 + 2], w3 = sW4[k * 4 + 3];
        h0.x += xk * w0.x; h0.y += xk * w0.y; h0.z += xk * w0.z; h0.w += xk * w0.w;
        h1.x += xk * w1.x; h1.y += xk * w1.y; h1.z += xk * w1.z; h1.w += xk * w1.w;
        h2.x += xk * w2.x; h2.y += xk * w2.y; h2.z += xk * w2.z; h2.w += xk * w2.w;
        h3.x += xk * w3.x; h3.y += xk * w3.y; h3.z += xk * w3.z; h3.w += xk * w3.w;
    }

    float as0 = h0.x*ss[0] + h0.y*ss[1] + h0.z*ss[2] + h0.w*ss[3]
              + h1.x*ss[4] + h1.y*ss[5] + h1.z*ss[6] + h1.w*ss[7];
    float as1 = h2.x*ss[8] + h2.y*ss[9] + h2.z*ss[10] + h2.w*ss[11]
              + h3.x*ss[12] + h3.y*ss[13] + h3.z*ss[14] + h3.w*ss[15];
    float ad0 = h0.x*sd[0] + h0.y*sd[1] + h0.z*sd[2] + h0.w*sd[3]
              + h1.x*sd[4] + h1.y*sd[5] + h1.z*sd[6] + h1.w*sd[7];
    float ad1 = h2.x*sd[8] + h2.y*sd[9] + h2.z*sd[10] + h2.w*sd[11]
              + h3.x*sd[12] + h3.y*sd[13] + h3.z*sd[14] + h3.w*sd[15];

    float4 p0, p1;
    half2* ha = (half2*)&p0;
    half2* hb = (half2*)&p1;
    ha[0] = __floats2half2_rn(h0.x, h0.y); ha[1] = __floats2half2_rn(h0.z, h0.w);
    ha[2] = __floats2half2_rn(h1.x, h1.y); ha[3] = __floats2half2_rn(h1.z, h1.w);
    hb[0] = __floats2half2_rn(h2.x, h2.y); hb[1] = __floats2half2_rn(h2.z, h2.w);
    hb[2] = __floats2half2_rn(h3.x, h3.y); hb[3] = __floats2half2_rn(h3.z, h3.w);

    size_t base = (size_t)n * 32 + t * 2;
    g_rec1[base]     = p0;
    g_rec1[base + 1] = p1;
    g_as12[(size_t)n * 16 + t] = make_float2(as0, as1);
    g_ad12[(size_t)n * 16 + t] = make_float2(ad0, ad1);
}

// ================= K2: warp-per-node layer-1 aggregate, flat batch-4 loop =================

__device__ __forceinline__ void unpack8(const float4& p, float* f) {
    const half2* hh = (const half2*)&p;
#pragma unroll
    for (int j = 0; j < 4; j++) {
        float2 v = __half22float2(hh[j]);
        f[2 * j] = v.x; f[2 * j + 1] = v.y;
    }
}

__global__ void __launch_bounds__(256) k2_agg1(
    const float* __restrict__ W2,
    const float* __restrict__ a2s, const float* __restrict__ a2d)
{
    __shared__ float sW[64], s2s[4], s2d[4];
    int tid = threadIdx.x;
    if (tid < 64) sW[tid] = W2[tid];
    if (tid >= 64 && tid < 68) { s2s[tid - 64] = a2s[tid - 64]; s2d[tid - 64] = a2d[tid - 64]; }
    __syncthreads();

    int n = blockIdx.x * 8 + (tid >> 5);
    if (n >= NN) return;
    int lane = tid & 31;
    int hd   = lane & 1;                 // head

    const char*  rbase = (const char*)g_rec1;
    const float* gas   = (const float*)g_as12;
    const float* gad   = (const float*)g_ad12;
    unsigned lane16 = (unsigned)lane * 16u;

    float ad = gad[(size_t)n * 32 + lane];      // my dst logit (fp32)

    int dp = g_deg[n];                          // padded degree (multiple of 4, or 0)
    const int4* cp = (const int4*)(g_colp + (size_t)n * CAP);

    float acc[8] = {0.f, 0.f, 0.f, 0.f, 0.f, 0.f, 0.f, 0.f};
    float den = 0.f;

    auto proc = [&](const float4& p, float as) {
        float g[8];
        unpack8(p, g);
        float z = as + ad; z = z > 0.f ? z : NEG * z;
        float w = __expf(z);
        den += w;
#pragma unroll
        for (int d = 0; d < 8; d++) acc[d] += w * g[d];
    };

    for (int b = 0; b < dp; b += 4) {
        int4 cs = cp[b >> 2];
        float4 c0 = *(const float4*)(rbase + (size_t)((unsigned)cs.x * 512u + lane16));
        float4 c1 = *(const float4*)(rbase + (size_t)((unsigned)cs.y * 512u + lane16));
        float4 c2 = *(const float4*)(rbase + (size_t)((unsigned)cs.z * 512u + lane16));
        float4 c3 = *(const float4*)(rbase + (size_t)((unsigned)cs.w * 512u + lane16));
        float ca0 = gas[(size_t)cs.x * 32 + lane];
        float ca1 = gas[(size_t)cs.y * 32 + lane];
        float ca2 = gas[(size_t)cs.z * 32 + lane];
        float ca3 = gas[(size_t)cs.w * 32 + lane];
        proc(c0, ca0);                       // unconditional: sentinels give w = 0
        proc(c1, ca1);
        proc(c2, ca2);
        proc(c3, ca3);
    }

    float inv = 1.f / fmaxf(den, 1e-16f);
    float o[8];
#pragma unroll
    for (int d = 0; d < 8; d++) {
        float v = acc[d] * inv;
        o[d] = v > 0.f ? v : (__expf(v) - 1.f);              // ELU
    }

    // W2: my 8 rows -> partial h2o[4]; pair-sum with the other head via shfl_xor(1)
    const float* sWh = sW + hd * 32;
    float h2o[4] = {0.f, 0.f, 0.f, 0.f};
#pragma unroll
    for (int d = 0; d < 8; d++) {
        float od = o[d];
#pragma unroll
        for (int c2 = 0; c2 < 4; c2++) h2o[c2] += od * sWh[d * 4 + c2];
    }
#pragma unroll
    for (int c2 = 0; c2 < 4; c2++) h2o[c2] += __shfl_xor_sync(0xffffffffu, h2o[c2], 1);

    if (hd == 0) {
        int t = lane >> 1;
        float as2 = h2o[0]*s2s[0] + h2o[1]*s2s[1] + h2o[2]*s2s[2] + h2o[3]*s2s[3];
        float ad2 = h2o[0]*s2d[0] + h2o[1]*s2d[1] + h2o[2]*s2d[2] + h2o[3]*s2d[3];
        float4 w4;
        half2* hw = (half2*)&w4;
        hw[0] = __floats2half2_rn(h2o[0], h2o[1]);
        hw[1] = __floats2half2_rn(h2o[2], h2o[3]);
        w4.z = as2;
        w4.w = ad2;
        g_rec2x[(size_t)n * 16 + t] = w4;
    }
}

// ================= K3: warp-per-node layer-2 aggregate + MLP, flat batch-4 loop ===========

__global__ void __launch_bounds__(256) k3_agg2(
    const float* __restrict__ mw, const float* __restrict__ mb,
    float* __restrict__ out)
{
    __shared__ float sm[4], sb;
    int tid = threadIdx.x;
    if (tid < 4) sm[tid] = mw[tid];
    if (tid == 4) sb = mb[0];
    __syncthreads();

    int n = blockIdx.x * 8 + (tid >> 5);
    if (n >= NN) return;
    int lane = tid & 31;
    int t    = lane & 15;
    int a    = lane >> 4;            // which edge of each pair this lane handles

    const char* rbase = (const char*)g_rec2x;
    unsigned t16 = (unsigned)t * 16u;

    float ad = g_rec2x[(size_t)n * 16 + t].w;   // my dst logit (fp32)

    int dp = g_deg[n];                          // padded degree (multiple of 4, or 0)
    const int* col = g_colp + (size_t)n * CAP;

    float a0 = 0.f, a1 = 0.f, a2 = 0.f, a3 = 0.f, den = 0.f;

    auto proc = [&](const float4& v) {
        const half2* hh = (const half2*)&v;
        float2 f0 = __half22float2(hh[0]), f1 = __half22float2(hh[1]);
        float z = v.z + ad; z = z > 0.f ? z : NEG * z;
        float w = __expf(z);
        den += w;
        a0 += w * f0.x; a1 += w * f0.y; a2 += w * f1.x; a3 += w * f1.y;
    };

    for (int b = 0; b < dp; b += 4) {
        int j0 = col[b + a], j1 = col[b + 2 + a];
        float4 v0 = *(const float4*)(rbase + (size_t)((unsigned)j0 * 256u + t16));
        float4 v1 = *(const float4*)(rbase + (size_t)((unsigned)j1 * 256u + t16));
        proc(v0);                            // unconditional: sentinels give w = 0
        proc(v1);
    }

    // combine the two edge-halves for each tick
    a0  += __shfl_down_sync(0xffffffffu, a0, 16);
    a1  += __shfl_down_sync(0xffffffffu, a1, 16);
    a2  += __shfl_down_sync(0xffffffffu, a2, 16);
    a3  += __shfl_down_sync(0xffffffffu, a3, 16);
    den += __shfl_down_sync(0xffffffffu, den, 16);

    if (a == 0) {
        float inv = 1.f / fmaxf(den, 1e-16f);
        float y = (a0 * sm[0] + a1 * sm[1] + a2 * sm[2] + a3 * sm[3]) * inv + sb;
        out[(size_t)t * NN + n] = y;
    }
}

// ================= launch =================

extern "C" void kernel_launch(void* const* d_in, const int* in_sizes, int n_in,
                              void* d_out, int out_size)
{
    const float* fw  = (const float*)d_in[0];
    const float* sw  = (const float*)d_in[1];
    const float* tw  = (const float*)d_in[2];
    const int*   idx = (const int*)  d_in[3];
    const int*   ei  = (const int*)  d_in[4];
    const float* W1  = (const float*)d_in[5];
    const float* a1s = (const float*)d_in[6];
    const float* a1d = (const float*)d_in[7];
    const float* W2  = (const float*)d_in[8];
    const float* a2s = (const float*)d_in[9];
    const float* a2d = (const float*)d_in[10];
    const float* mw  = (const float*)d_in[11];
    const float* mb  = (const float*)d_in[12];
    float* out = (float*)d_out;

    // k2 is the 4th kernel launch -> lands in the profiled slot
    k_init<<<(NN + 255) / 256, 256>>>((const float4*)fw, (const float4*)sw, (const float4*)tw);
    k_append<<<(NE + 255) / 256, 256>>>(ei);
    k1_features<<<(NN + 15) / 16, 256>>>(idx, W1, a1s, a1d);
    k2_agg1<<<(NN + 7) / 8, 256>>>(W2, a2s, a2d);
    k3_agg2<<<(NN + 7) / 8, 256>>>(mw, mb, out);
}

// round 14
// speedup vs baseline: 1.2383x; 1.0223x over previous
#include <cuda_runtime.h>
#include <cuda_fp16.h>

#define NWIRE 480
#define NT    16
#define NN    150000
#define NE    1800000
#define NEG   0.2f
#define CAP   64          // padded bucket capacity per node (deg ~ Poisson(12))
#define LOG2E 1.4426950408889634f

// ---- static device scratch ----
__device__ int    g_deg[NN];                    // per-node degree; after k1: PADDED degree
__device__ int    g_colp[(size_t)NN * CAP];     // padded adjacency: src list per dst
// transposed wires: wire-major [w][t], one float4 per (w,t)
__device__ float4 g_wt1[NWIRE * NT];
__device__ float4 g_wt2[NWIRE * NT];
__device__ float4 g_wt3[NWIRE * NT];
// rec1: per node 512B = 16 ticks x 32B (h[16] fp16); +1 sentinel node (index NN, all zero)
__device__ float4 g_rec1[(size_t)(NN + 1) * 32];
// layer-1 attention logits (PRE-SCALED by log2e), lane-indexed; sentinel = -1e30
__device__ float2 g_as12[(size_t)(NN + 1) * 16];
__device__ float2 g_ad12[(size_t)(NN + 1) * 16];
// rec2: per (n,t) 16B {h2[0..3] fp16, as2*log2e f32, ad2*log2e f32}; sentinel as2 = -1e30
__device__ float4 g_rec2x[(size_t)(NN + 1) * 16];

// ---- Blackwell mixed-precision fma: acc(f32) += a(f16) * b(f16) ----
__device__ __forceinline__ void mfma(float& d, unsigned short a, unsigned short b) {
    asm("fma.rn.f32.f16 %0, %1, %2, %0;" : "+f"(d) : "h"(a), "h"(b));
}
__device__ __forceinline__ void unpk(unsigned r, unsigned short& lo, unsigned short& hi) {
    asm("mov.b32 {%0, %1}, %2;" : "=h"(lo), "=h"(hi) : "r"(r));
}
__device__ __forceinline__ float ex2f(float x) {
    float r; asm("ex2.approx.f32 %0, %1;" : "=f"(r) : "f"(x)); return r;
}
__device__ __forceinline__ unsigned short f2h(float x) {
    unsigned short r; asm("cvt.rn.f16.f32 %0, %1;" : "=h"(r) : "f"(x)); return r;
}
#define ONE16 ((unsigned short)0x3C00)

// ================= K_init: zero deg + transpose wires + write sentinel records =============

__global__ void k_init(const float4* __restrict__ w1, const float4* __restrict__ w2,
                       const float4* __restrict__ w3)
{
    int i = blockIdx.x * blockDim.x + threadIdx.x;
    if (i < NN) g_deg[i] = 0;
    if (i < NT * NWIRE) {
        int t = i / NWIRE, w = i % NWIRE;
        int o = w * NT + t;
        g_wt1[o] = w1[i];
        g_wt2[o] = w2[i];
        g_wt3[o] = w3[i];
    }
    if (i < 32) {
        g_rec1[(size_t)NN * 32 + i] = make_float4(0.f, 0.f, 0.f, 0.f);
        if (i < 16) {
            g_as12[(size_t)NN * 16 + i] = make_float2(-1e30f, -1e30f);
            g_ad12[(size_t)NN * 16 + i] = make_float2(0.f, 0.f);
            g_rec2x[(size_t)NN * 16 + i] = make_float4(0.f, 0.f, -1e30f, 0.f);
        }
    }
}

// ================= K_append: one-pass padded-CSR build =================

__global__ void k_append(const int* __restrict__ ei) {
    int e = blockIdx.x * blockDim.x + threadIdx.x;
    if (e < NE) {
        int d   = ei[NE + e];
        int pos = atomicAdd(&g_deg[d], 1);
        if (pos < CAP) g_colp[(size_t)d * CAP + pos] = ei[e];
    }
}

// ================= K1: features + prescaled fp32 logits; pads adjacency to 4-multiple ======

__global__ void __launch_bounds__(256) k1_features(
    const int* __restrict__ idx, const float* __restrict__ W1,
    const float* __restrict__ a1s, const float* __restrict__ a1d)
{
    __shared__ float4 sW4[48];                  // W1 [12][16] as 12 rows x 4 float4
    __shared__ float  ss[16], sd[16];
    int tid = threadIdx.x;
    if (tid < 48) sW4[tid] = ((const float4*)W1)[tid];
    if (tid >= 64 && tid < 80) ss[tid - 64] = a1s[tid - 64] * LOG2E;   // prescale
    if (tid >= 80 && tid < 96) sd[tid - 80] = a1d[tid - 80] * LOG2E;
    __syncthreads();

    int n = blockIdx.x * 16 + (tid >> 4);
    int t = tid & 15;
    if (n >= NN) return;

    // pad adjacency with sentinel (index NN) to a multiple of 4; store padded degree
    if (t == 0) {
        int dg = min(g_deg[n], CAP);
        int dp = min((dg + 3) & ~3, CAP);
        for (int j = dg; j < dp; j++) g_colp[(size_t)n * CAP + j] = NN;
        g_deg[n] = dp;
    }

    int i0 = idx[3 * n], i1 = idx[3 * n + 1], i2 = idx[3 * n + 2];
    float4 x0 = g_wt1[i0 * NT + t];   // 16 lanes of one node: 256B contiguous
    float4 x1 = g_wt2[i1 * NT + t];
    float4 x2 = g_wt3[i2 * NT + t];
    float x[12] = { x0.x, x0.y, x0.z, x0.w, x1.x, x1.y, x1.z, x1.w, x2.x, x2.y, x2.z, x2.w };

    float4 h0 = make_float4(0.f, 0.f, 0.f, 0.f);
    float4 h1 = h0, h2 = h0, h3 = h0;
#pragma unroll
    for (int k = 0; k < 12; k++) {
        float xk = x[k];
        float4 w0 = sW4[k * 4], w1 = sW4[k * 4 + 1], w2 = sW4[k * 4 + 2], w3 = sW4[k * 4 + 3];
        h0.x += xk * w0.x; h0.y += xk * w0.y; h0.z += xk * w0.z; h0.w += xk * w0.w;
        h1.x += xk * w1.x; h1.y += xk * w1.y; h1.z += xk * w1.z; h1.w += xk * w1.w;
        h2.x += xk * w2.x; h2.y += xk * w2.y; h2.z += xk * w2.z; h2.w += xk * w2.w;
        h3.x += xk * w3.x; h3.y += xk * w3.y; h3.z += xk * w3.z; h3.w += xk * w3.w;
    }

    float as0 = h0.x*ss[0] + h0.y*ss[1] + h0.z*ss[2] + h0.w*ss[3]
              + h1.x*ss[4] + h1.y*ss[5] + h1.z*ss[6] + h1.w*ss[7];
    float as1 = h2.x*ss[8] + h2.y*ss[9] + h2.z*ss[10] + h2.w*ss[11]
              + h3.x*ss[12] + h3.y*ss[13] + h3.z*ss[14] + h3.w*ss[15];
    float ad0 = h0.x*sd[0] + h0.y*sd[1] + h0.z*sd[2] + h0.w*sd[3]
              + h1.x*sd[4] + h1.y*sd[5] + h1.z*sd[6] + h1.w*sd[7];
    float ad1 = h2.x*sd[8] + h2.y*sd[9] + h2.z*sd[10] + h2.w*sd[11]
              + h3.x*sd[12] + h3.y*sd[13] + h3.z*sd[14] + h3.w*sd[15];

    float4 p0, p1;
    half2* ha = (half2*)&p0;
    half2* hb = (half2*)&p1;
    ha[0] = __floats2half2_rn(h0.x, h0.y); ha[1] = __floats2half2_rn(h0.z, h0.w);
    ha[2] = __floats2half2_rn(h1.x, h1.y); ha[3] = __floats2half2_rn(h1.z, h1.w);
    hb[0] = __floats2half2_rn(h2.x, h2.y); hb[1] = __floats2half2_rn(h2.z, h2.w);
    hb[2] = __floats2half2_rn(h3.x, h3.y); hb[3] = __floats2half2_rn(h3.z, h3.w);

    size_t base = (size_t)n * 32 + t * 2;
    g_rec1[base]     = p0;
    g_rec1[base + 1] = p1;
    g_as12[(size_t)n * 16 + t] = make_float2(as0, as1);
    g_ad12[(size_t)n * 16 + t] = make_float2(ad0, ad1);
}

// ================= K2: warp-per-node layer-1 aggregate, mixed-precision FMA ===============

__global__ void __launch_bounds__(256) k2_agg1(
    const float* __restrict__ W2,
    const float* __restrict__ a2s, const float* __restrict__ a2d)
{
    __shared__ float sW[64], s2s[4], s2d[4];
    int tid = threadIdx.x;
    if (tid < 64) sW[tid] = W2[tid];
    if (tid >= 64 && tid < 68) {
        s2s[tid - 64] = a2s[tid - 64] * LOG2E;   // prescale layer-2 logits
        s2d[tid - 64] = a2d[tid - 64] * LOG2E;
    }
    __syncthreads();

    int n = blockIdx.x * 8 + (tid >> 5);
    if (n >= NN) return;
    int lane = tid & 31;
    int hd   = lane & 1;                 // head

    const char*  rbase = (const char*)g_rec1;
    const float* gas   = (const float*)g_as12;
    const float* gad   = (const float*)g_ad12;
    unsigned lane16 = (unsigned)lane * 16u;

    float ad = gad[(size_t)n * 32 + lane];      // my dst logit (prescaled fp32)

    int dp = g_deg[n];                          // padded degree (multiple of 4, or 0)
    const int4* cp = (const int4*)(g_colp + (size_t)n * CAP);

    float acc[8] = {0.f, 0.f, 0.f, 0.f, 0.f, 0.f, 0.f, 0.f};
    float den = 0.f;

    auto proc = [&](const float4& p, float as) {
        const unsigned* pr = (const unsigned*)&p;
        unsigned short h0, h1, h2, h3, h4, h5, h6, h7;
        unpk(pr[0], h0, h1); unpk(pr[1], h2, h3);
        unpk(pr[2], h4, h5); unpk(pr[3], h6, h7);
        float z = as + ad;
        z = fmaxf(z, NEG * z);                  // leaky relu (commutes with log2e scale)
        unsigned short w16 = f2h(ex2f(z));
        mfma(den, w16, ONE16);                  // den += w (consistent with numerator)
        mfma(acc[0], w16, h0); mfma(acc[1], w16, h1);
        mfma(acc[2], w16, h2); mfma(acc[3], w16, h3);
        mfma(acc[4], w16, h4); mfma(acc[5], w16, h5);
        mfma(acc[6], w16, h6); mfma(acc[7], w16, h7);
    };

    for (int b = 0; b < dp; b += 4) {
        int4 cs = cp[b >> 2];
        float4 c0 = *(const float4*)(rbase + (size_t)((unsigned)cs.x * 512u + lane16));
        float4 c1 = *(const float4*)(rbase + (size_t)((unsigned)cs.y * 512u + lane16));
        float4 c2 = *(const float4*)(rbase + (size_t)((unsigned)cs.z * 512u + lane16));
        float4 c3 = *(const float4*)(rbase + (size_t)((unsigned)cs.w * 512u + lane16));
        float ca0 = gas[(size_t)cs.x * 32 + lane];
        float ca1 = gas[(size_t)cs.y * 32 + lane];
        float ca2 = gas[(size_t)cs.z * 32 + lane];
        float ca3 = gas[(size_t)cs.w * 32 + lane];
        proc(c0, ca0);                       // unconditional: sentinels give w = 0
        proc(c1, ca1);
        proc(c2, ca2);
        proc(c3, ca3);
    }

    float inv = 1.f / fmaxf(den, 1e-16f);
    float o[8];
#pragma unroll
    for (int d = 0; d < 8; d++) {
        float v = acc[d] * inv;
        o[d] = v > 0.f ? v : (__expf(v) - 1.f);              // ELU
    }

    // W2: my 8 rows -> partial h2o[4]; pair-sum with the other head via shfl_xor(1)
    const float* sWh = sW + hd * 32;
    float h2o[4] = {0.f, 0.f, 0.f, 0.f};
#pragma unroll
    for (int d = 0; d < 8; d++) {
        float od = o[d];
#pragma unroll
        for (int c2 = 0; c2 < 4; c2++) h2o[c2] += od * sWh[d * 4 + c2];
    }
#pragma unroll
    for (int c2 = 0; c2 < 4; c2++) h2o[c2] += __shfl_xor_sync(0xffffffffu, h2o[c2], 1);

    if (hd == 0) {
        int t = lane >> 1;
        float as2 = h2o[0]*s2s[0] + h2o[1]*s2s[1] + h2o[2]*s2s[2] + h2o[3]*s2s[3];  // prescaled
        float ad2 = h2o[0]*s2d[0] + h2o[1]*s2d[1] + h2o[2]*s2d[2] + h2o[3]*s2d[3];
        float4 w4;
        half2* hw = (half2*)&w4;
        hw[0] = __floats2half2_rn(h2o[0], h2o[1]);
        hw[1] = __floats2half2_rn(h2o[2], h2o[3]);
        w4.z = as2;
        w4.w = ad2;
        g_rec2x[(size_t)n * 16 + t] = w4;
    }
}

// ================= K3: warp-per-node layer-2 aggregate + MLP, mixed-precision FMA =========

__global__ void __launch_bounds__(256) k3_agg2(
    const float* __restrict__ mw, const float* __restrict__ mb,
    float* __restrict__ out)
{
    __shared__ float sm[4], sb;
    int tid = threadIdx.x;
    if (tid < 4) sm[tid] = mw[tid];
    if (tid == 4) sb = mb[0];
    __syncthreads();

    int n = blockIdx.x * 8 + (tid >> 5);
    if (n >= NN) return;
    int lane = tid & 31;
    int t    = lane & 15;
    int a    = lane >> 4;            // which edge of each pair this lane handles

    const char* rbase = (const char*)g_rec2x;
    unsigned t16 = (unsigned)t * 16u;

    float ad = g_rec2x[(size_t)n * 16 + t].w;   // my dst logit (prescaled fp32)

    int dp = g_deg[n];                          // padded degree (multiple of 4, or 0)
    const int* col = g_colp + (size_t)n * CAP;

    float a0 = 0.f, a1 = 0.f, a2 = 0.f, a3 = 0.f, den = 0.f;

    auto proc = [&](const float4& v) {
        const unsigned* pr = (const unsigned*)&v;
        unsigned short h0, h1, h2, h3;
        unpk(pr[0], h0, h1); unpk(pr[1], h2, h3);
        float z = v.z + ad;
        z = fmaxf(z, NEG * z);
        unsigned short w16 = f2h(ex2f(z));
        mfma(den, w16, ONE16);
        mfma(a0, w16, h0); mfma(a1, w16, h1);
        mfma(a2, w16, h2); mfma(a3, w16, h3);
    };

    for (int b = 0; b < dp; b += 4) {
        int j0 = col[b + a], j1 = col[b + 2 + a];
        float4 v0 = *(const float4*)(rbase + (size_t)((unsigned)j0 * 256u + t16));
        float4 v1 = *(const float4*)(rbase + (size_t)((unsigned)j1 * 256u + t16));
        proc(v0);                            // unconditional: sentinels give w = 0
        proc(v1);
    }

    // combine the two edge-halves for each tick
    a0  += __shfl_down_sync(0xffffffffu, a0, 16);
    a1  += __shfl_down_sync(0xffffffffu, a1, 16);
    a2  += __shfl_down_sync(0xffffffffu, a2, 16);
    a3  += __shfl_down_sync(0xffffffffu, a3, 16);
    den += __shfl_down_sync(0xffffffffu, den, 16);

    if (a == 0) {
        float inv = 1.f / fmaxf(den, 1e-16f);
        float y = (a0 * sm[0] + a1 * sm[1] + a2 * sm[2] + a3 * sm[3]) * inv + sb;
        out[(size_t)t * NN + n] = y;
    }
}

// ================= launch =================

extern "C" void kernel_launch(void* const* d_in, const int* in_sizes, int n_in,
                              void* d_out, int out_size)
{
    const float* fw  = (const float*)d_in[0];
    const float* sw  = (const float*)d_in[1];
    const float* tw  = (const float*)d_in[2];
    const int*   idx = (const int*)  d_in[3];
    const int*   ei  = (const int*)  d_in[4];
    const float* W1  = (const float*)d_in[5];
    const float* a1s = (const float*)d_in[6];
    const float* a1d = (const float*)d_in[7];
    const float* W2  = (const float*)d_in[8];
    const float* a2s = (const float*)d_in[9];
    const float* a2d = (const float*)d_in[10];
    const float* mw  = (const float*)d_in[11];
    const float* mb  = (const float*)d_in[12];
    float* out = (float*)d_out;

    // k2 is the 4th kernel launch -> lands in the profiled slot
    k_init<<<(NN + 255) / 256, 256>>>((const float4*)fw, (const float4*)sw, (const float4*)tw);
    k_append<<<(NE + 255) / 256, 256>>>(ei);
    k1_features<<<(NN + 15) / 16, 256>>>(idx, W1, a1s, a1d);
    k2_agg1<<<(NN + 7) / 8, 256>>>(W2, a2s, a2d);
    k3_agg2<<<(NN + 7) / 8, 256>>>(mw, mb, out);
}